// round 3
// baseline (speedup 1.0000x reference)
#include <cuda_runtime.h>

#define HH 128
#define WW 128
#define HWSZ 16384
#define CIN 64
#define CMID 16
#define NMAX 4

#define TX 16
#define TY 8
#define RAD 4
#define HX 24
#define HY 16
#define HP (HX * HY)   // 384 halo pixels
#define FSTR 20        // floats per halo pixel in smem (16 used, pad to 20 -> conflict-free LDS.128)

// Scratch (device globals — no allocation allowed)
__device__ float g_f1[NMAX * HWSZ * CMID];   // [N, HW, 16]
__device__ float g_f2[NMAX * HWSZ * CMID];   // [N, HW, 16]
__device__ float g_oup[NMAX * HWSZ * 2];     // [N, HW, 2]

typedef unsigned long long u64;

__device__ __forceinline__ u64 pack2(float a, float b) {
    u64 r; asm("mov.b64 %0, {%1,%2};" : "=l"(r) : "f"(a), "f"(b)); return r;
}
__device__ __forceinline__ float2 unpack2(u64 v) {
    float2 r; asm("mov.b64 {%0,%1}, %2;" : "=f"(r.x), "=f"(r.y) : "l"(v)); return r;
}
__device__ __forceinline__ u64 fma2(u64 a, u64 b, u64 c) {
    u64 d; asm("fma.rn.f32x2 %0, %1, %2, %3;" : "=l"(d) : "l"(a), "l"(b), "l"(c)); return d;
}
__device__ __forceinline__ u64 add2(u64 a, u64 b) {
    u64 d; asm("add.rn.f32x2 %0, %1, %2;" : "=l"(d) : "l"(a), "l"(b)); return d;
}

__device__ __forceinline__ int refl(int i, int n) {
    if (i < 0) i = -i;
    if (i >= n) i = 2 * n - 2 - i;
    return i;
}

// Kernel 1: one 1x1 conv (64->16) per blockIdx.y (0: f1, 1: f2), f32x2-packed.
// conv==0 path also does the bilinear align-corners upsample of out.
__global__ __launch_bounds__(256) void prep_kernel(
    const float* __restrict__ delta,
    const float* __restrict__ outc,
    const float* __restrict__ w1, const float* __restrict__ b1,
    const float* __restrict__ w2, const float* __restrict__ b2,
    int N) {
    __shared__ float s_w[CMID * CIN];
    const int conv = blockIdx.y;
    const float* w = conv ? w2 : w1;
    const float* b = conv ? b2 : b1;
    float* gout = conv ? g_f2 : g_f1;
    for (int i = threadIdx.x; i < CMID * CIN; i += 256) s_w[i] = w[i];
    __syncthreads();

    int p = blockIdx.x * 256 + threadIdx.x;
    if (p >= N * HWSZ) return;
    int n = p >> 14;
    int yx = p & (HWSZ - 1);

    u64 acc[CMID];
#pragma unroll
    for (int o = 0; o < CMID; o++) acc[o] = 0ULL;  // bit pattern 0 == (0.f, 0.f)

    const float* dptr = delta + (size_t)n * CIN * HWSZ + yx;
#pragma unroll 2
    for (int c0 = 0; c0 < CIN; c0 += 4) {
        float d0 = __ldg(dptr + (c0 + 0) * HWSZ);
        float d1 = __ldg(dptr + (c0 + 1) * HWSZ);
        float d2 = __ldg(dptr + (c0 + 2) * HWSZ);
        float d3 = __ldg(dptr + (c0 + 3) * HWSZ);
        u64 dA = pack2(d0, d1);
        u64 dB = pack2(d2, d3);
#pragma unroll
        for (int o = 0; o < CMID; o++) {
            const u64* wp = (const u64*)(s_w + o * CIN + c0);  // 16B aligned
            acc[o] = fma2(dA, wp[0], acc[o]);
            acc[o] = fma2(dB, wp[1], acc[o]);
        }
    }

    float4* fo = (float4*)(gout + (size_t)p * CMID);
#pragma unroll
    for (int j = 0; j < 4; j++) {
        float2 e0 = unpack2(acc[4 * j + 0]);
        float2 e1 = unpack2(acc[4 * j + 1]);
        float2 e2 = unpack2(acc[4 * j + 2]);
        float2 e3 = unpack2(acc[4 * j + 3]);
        fo[j] = make_float4(b[4 * j + 0] + e0.x + e0.y,
                            b[4 * j + 1] + e1.x + e1.y,
                            b[4 * j + 2] + e2.x + e2.y,
                            b[4 * j + 3] + e3.x + e3.y);
    }

    if (conv == 0) {
        // Bilinear upsample (align_corners=True) of out [N,2,64,64]
        int y = yx >> 7, x = yx & 127;
        const float scl = 63.0f / 127.0f;
        float sy = y * scl, sx = x * scl;
        int y0i = (int)sy, x0i = (int)sx;
        if (y0i > 62) y0i = 62;
        if (x0i > 62) x0i = 62;
        float wy = sy - y0i, wx = sx - x0i;
        const float* ob = outc + (size_t)n * 2 * 4096;
#pragma unroll
        for (int c = 0; c < 2; c++) {
            const float* oc = ob + c * 4096;
            float v00 = oc[y0i * 64 + x0i];
            float v01 = oc[y0i * 64 + x0i + 1];
            float v10 = oc[(y0i + 1) * 64 + x0i];
            float v11 = oc[(y0i + 1) * 64 + x0i + 1];
            float top = v00 * (1.0f - wx) + v01 * wx;
            float bot = v10 * (1.0f - wx) + v11 * wx;
            g_oup[(size_t)p * 2 + c] = top * (1.0f - wy) + bot * wy;
        }
    }
}

// Kernel 2: 16x8 pixel tile, 4 threads per pixel (taps k = h + 4j).
// dist via |f1|^2 + |f2|^2 - 2 f1.f2 with precomputed -gd*|f2|^2 in halo,
// f1 pre-scaled by 2*gd, dot via packed fma.rn.f32x2. Plain exp (no max).
__global__ __launch_bounds__(512) void main_kernel(
    const float* __restrict__ ab,
    const float* __restrict__ gdp,
    const float* __restrict__ gsp,
    float* __restrict__ outr) {
    __shared__ float s_f2[HP * FSTR];   // 30720 B
    __shared__ float4 s_oc[HP];         //  6144 B : (ou.x, ou.y, -gd*|f2|^2, 0)
    __shared__ float4 s_red[512];       //  8192 B

    const int tid = threadIdx.x;
    const int x0 = blockIdx.x * TX, y0 = blockIdx.y * TY;
    const int n = blockIdx.z;
    const float gd = *gdp;
    const float gs = *gsp;

    // Halo load with reflect mapping + norm precompute
    for (int i = tid; i < HP; i += 512) {
        int hy = i / HX, hx = i - hy * HX;
        int gy = refl(y0 - RAD + hy, HH);
        int gx = refl(x0 - RAD + hx, WW);
        int gp = (n << 14) + (gy << 7) + gx;
        const float4* src = (const float4*)(g_f2 + (size_t)gp * CMID);
        float4 a0 = src[0], a1 = src[1], a2 = src[2], a3 = src[3];
        float nf2 = 0.f;
        nf2 = fmaf(a0.x, a0.x, fmaf(a0.y, a0.y, fmaf(a0.z, a0.z, fmaf(a0.w, a0.w, nf2))));
        nf2 = fmaf(a1.x, a1.x, fmaf(a1.y, a1.y, fmaf(a1.z, a1.z, fmaf(a1.w, a1.w, nf2))));
        nf2 = fmaf(a2.x, a2.x, fmaf(a2.y, a2.y, fmaf(a2.z, a2.z, fmaf(a2.w, a2.w, nf2))));
        nf2 = fmaf(a3.x, a3.x, fmaf(a3.y, a3.y, fmaf(a3.z, a3.z, fmaf(a3.w, a3.w, nf2))));
        float4* dst = (float4*)(s_f2 + i * FSTR);   // 80B stride -> 16B aligned
        dst[0] = a0; dst[1] = a1; dst[2] = a2; dst[3] = a3;
        float2 ov = *(const float2*)(g_oup + (size_t)gp * 2);
        s_oc[i] = make_float4(ov.x, ov.y, -gd * nf2, 0.f);
    }
    __syncthreads();

    const int pix = tid & 127;
    const int h = tid >> 7;
    const int px = pix & 15, py = pix >> 4;
    const int yx = ((y0 + py) << 7) + (x0 + px);
    const int p = (n << 14) + yx;

    // f1 scaled by 2*gd, packed in pairs; nf1 for the -gd*|f1|^2 term
    u64 f1s[8];
    float nf1 = 0.f;
    {
        const float4* f1p = (const float4*)(g_f1 + (size_t)p * CMID);
        const float tg = 2.f * gd;
#pragma unroll
        for (int j = 0; j < 4; j++) {
            float4 v = f1p[j];
            nf1 = fmaf(v.x, v.x, fmaf(v.y, v.y, fmaf(v.z, v.z, fmaf(v.w, v.w, nf1))));
            f1s[2 * j + 0] = pack2(tg * v.x, tg * v.y);
            f1s[2 * j + 1] = pack2(tg * v.z, tg * v.w);
        }
    }
    const float c1 = -gd * nf1;

    const float* abp = ab + (size_t)n * 81 * HWSZ + yx + (size_t)h * HWSZ;
    const int ntaps = (h == 0) ? 21 : 20;
    int dx = h;            // first tap k=h -> dy=0, dx=h (h<9)
    int hb = py * HX + px; // row base; advances by HX when dy++

    float s = 0.f, a0 = 0.f, a1 = 0.f;
    float abv = __ldg(abp);

#pragma unroll 2
    for (int j = 0; j < ntaps; j++) {
        const float* nab = (j + 1 < ntaps) ? (abp + 4 * HWSZ) : abp;
        float abn = __ldg(nab);

        int hidx = hb + dx;
        const ulonglong2* fp = (const ulonglong2*)(s_f2 + hidx * FSTR);
        ulonglong2 q0 = fp[0], q1 = fp[1];
        u64 A = fma2(f1s[0], q0.x, 0ULL);
        u64 B = fma2(f1s[1], q0.y, 0ULL);
        A = fma2(f1s[2], q1.x, A);
        B = fma2(f1s[3], q1.y, B);
        ulonglong2 q2 = fp[2], q3 = fp[3];
        A = fma2(f1s[4], q2.x, A);
        B = fma2(f1s[5], q2.y, B);
        A = fma2(f1s[6], q3.x, A);
        B = fma2(f1s[7], q3.y, B);
        A = add2(A, B);
        float2 dp = unpack2(A);
        float4 oc = s_oc[hidx];

        float logit = fmaf(gs, abv, c1 + oc.z + dp.x + dp.y);
        float w = __expf(logit);
        s += w;
        a0 = fmaf(w, oc.x, a0);
        a1 = fmaf(w, oc.y, a1);

        abv = abn;
        abp = nab;
        dx += 4;
        if (dx >= 9) { dx -= 9; hb += HX; }
    }

    s_red[tid] = make_float4(s, a0, a1, 0.f);
    __syncthreads();

    if (tid < 128) {
        float4 r0 = s_red[tid];
        float4 r1 = s_red[tid + 128];
        float4 r2 = s_red[tid + 256];
        float4 r3 = s_red[tid + 384];
        float ss = (r0.x + r1.x) + (r2.x + r3.x);
        float inv = 1.f / ss;
        float o0 = ((r0.y + r1.y) + (r2.y + r3.y)) * inv;
        float o1 = ((r0.z + r1.z) + (r2.z + r3.z)) * inv;
        outr[((size_t)(n * 2) << 14) + yx] = o0;
        outr[((size_t)(n * 2 + 1) << 14) + yx] = o1;
    }
}

extern "C" void kernel_launch(void* const* d_in, const int* in_sizes, int n_in,
                              void* d_out, int out_size) {
    const float* delta = (const float*)d_in[0];
    const float* outc  = (const float*)d_in[1];
    const float* ab    = (const float*)d_in[2];
    const float* w1    = (const float*)d_in[3];
    const float* b1    = (const float*)d_in[4];
    const float* w2    = (const float*)d_in[5];
    const float* b2    = (const float*)d_in[6];
    const float* gd    = (const float*)d_in[7];
    const float* gs    = (const float*)d_in[8];

    int N = in_sizes[0] / (CIN * HWSZ);
    if (N > NMAX) N = NMAX;

    prep_kernel<<<dim3((N * HWSZ + 255) / 256, 2), 256>>>(delta, outc, w1, b1, w2, b2, N);
    main_kernel<<<dim3(WW / TX, HH / TY, N), dim3(512)>>>(ab, gd, gs, (float*)d_out);
}

// round 4
// speedup vs baseline: 1.6027x; 1.6027x over previous
#include <cuda_runtime.h>

#define HH 128
#define WW 128
#define HWSZ 16384
#define CIN 64
#define CMID 16
#define NMAX 4

#define TX 16
#define TY 8
#define RAD 4
#define HX 24
#define HY 16
#define HP (HX * HY)   // 384 halo pixels
#define FSTR 20        // floats per halo pixel (16 f2 + norm + ou.x + ou.y + pad)

// Scratch (device globals — no allocation allowed)
__device__ float g_f1[NMAX * HWSZ * CMID];   // [N, HW, 16]
__device__ float g_f2[NMAX * HWSZ * CMID];   // [N, HW, 16]
__device__ float g_oup[NMAX * HWSZ * 2];     // [N, HW, 2]

typedef unsigned long long u64;

__device__ __forceinline__ u64 pack2(float a, float b) {
    u64 r; asm("mov.b64 %0, {%1,%2};" : "=l"(r) : "f"(a), "f"(b)); return r;
}
__device__ __forceinline__ float2 unpack2(u64 v) {
    float2 r; asm("mov.b64 {%0,%1}, %2;" : "=f"(r.x), "=f"(r.y) : "l"(v)); return r;
}
__device__ __forceinline__ u64 fma2(u64 a, u64 b, u64 c) {
    u64 d; asm("fma.rn.f32x2 %0, %1, %2, %3;" : "=l"(d) : "l"(a), "l"(b), "l"(c)); return d;
}
__device__ __forceinline__ u64 add2(u64 a, u64 b) {
    u64 d; asm("add.rn.f32x2 %0, %1, %2;" : "=l"(d) : "l"(a), "l"(b)); return d;
}

__device__ __forceinline__ int refl(int i, int n) {
    if (i < 0) i = -i;
    if (i >= n) i = 2 * n - 2 - i;
    return i;
}

// Kernel 1: BOTH 1x1 convs (64->16) in one pass over delta (read once),
// f32x2-packed accumulators, plus bilinear align-corners upsample of out.
__global__ __launch_bounds__(128) void prep_kernel(
    const float* __restrict__ delta,
    const float* __restrict__ outc,
    const float* __restrict__ w1, const float* __restrict__ b1,
    const float* __restrict__ w2, const float* __restrict__ b2,
    int N) {
    __shared__ float s_w1[CMID * CIN];
    __shared__ float s_w2[CMID * CIN];
    for (int i = threadIdx.x; i < CMID * CIN; i += 128) {
        s_w1[i] = w1[i];
        s_w2[i] = w2[i];
    }
    __syncthreads();

    int p = blockIdx.x * 128 + threadIdx.x;
    if (p >= N * HWSZ) return;
    int n = p >> 14;
    int yx = p & (HWSZ - 1);

    u64 acc1[CMID], acc2[CMID];
#pragma unroll
    for (int o = 0; o < CMID; o++) { acc1[o] = 0ULL; acc2[o] = 0ULL; }

    const float* dptr = delta + (size_t)n * CIN * HWSZ + yx;
#pragma unroll 1
    for (int c0 = 0; c0 < CIN; c0 += 4) {
        float d0 = __ldg(dptr + (c0 + 0) * HWSZ);
        float d1 = __ldg(dptr + (c0 + 1) * HWSZ);
        float d2 = __ldg(dptr + (c0 + 2) * HWSZ);
        float d3 = __ldg(dptr + (c0 + 3) * HWSZ);
        u64 dA = pack2(d0, d1);
        u64 dB = pack2(d2, d3);
#pragma unroll
        for (int o = 0; o < CMID; o++) {
            const u64* wa = (const u64*)(s_w1 + o * CIN + c0);
            const u64* wb = (const u64*)(s_w2 + o * CIN + c0);
            acc1[o] = fma2(dA, wa[0], acc1[o]);
            acc1[o] = fma2(dB, wa[1], acc1[o]);
            acc2[o] = fma2(dA, wb[0], acc2[o]);
            acc2[o] = fma2(dB, wb[1], acc2[o]);
        }
    }

    float4* f1o = (float4*)(g_f1 + (size_t)p * CMID);
    float4* f2o = (float4*)(g_f2 + (size_t)p * CMID);
#pragma unroll
    for (int j = 0; j < 4; j++) {
        float2 e0 = unpack2(acc1[4 * j + 0]);
        float2 e1 = unpack2(acc1[4 * j + 1]);
        float2 e2 = unpack2(acc1[4 * j + 2]);
        float2 e3 = unpack2(acc1[4 * j + 3]);
        f1o[j] = make_float4(b1[4 * j + 0] + e0.x + e0.y,
                             b1[4 * j + 1] + e1.x + e1.y,
                             b1[4 * j + 2] + e2.x + e2.y,
                             b1[4 * j + 3] + e3.x + e3.y);
        float2 g0 = unpack2(acc2[4 * j + 0]);
        float2 g1 = unpack2(acc2[4 * j + 1]);
        float2 g2 = unpack2(acc2[4 * j + 2]);
        float2 g3 = unpack2(acc2[4 * j + 3]);
        f2o[j] = make_float4(b2[4 * j + 0] + g0.x + g0.y,
                             b2[4 * j + 1] + g1.x + g1.y,
                             b2[4 * j + 2] + g2.x + g2.y,
                             b2[4 * j + 3] + g3.x + g3.y);
    }

    // Bilinear upsample (align_corners=True) of out [N,2,64,64]
    int y = yx >> 7, x = yx & 127;
    const float scl = 63.0f / 127.0f;
    float sy = y * scl, sx = x * scl;
    int y0i = (int)sy, x0i = (int)sx;
    if (y0i > 62) y0i = 62;
    if (x0i > 62) x0i = 62;
    float wy = sy - y0i, wx = sx - x0i;
    const float* ob = outc + (size_t)n * 2 * 4096;
#pragma unroll
    for (int c = 0; c < 2; c++) {
        const float* oc = ob + c * 4096;
        float v00 = oc[y0i * 64 + x0i];
        float v01 = oc[y0i * 64 + x0i + 1];
        float v10 = oc[(y0i + 1) * 64 + x0i];
        float v11 = oc[(y0i + 1) * 64 + x0i + 1];
        float top = v00 * (1.0f - wx) + v01 * wx;
        float bot = v10 * (1.0f - wx) + v11 * wx;
        g_oup[(size_t)p * 2 + c] = top * (1.0f - wy) + bot * wy;
    }
}

// Kernel 2: 16x8 pixel tile, 128 threads, ONE thread per pixel.
// dist via |f1|^2 + |f2|^2 - 2 f1.f2: -gd*|f2|^2 precomputed into the halo pad,
// f1 pre-scaled by 2*gd, dot via packed fma.rn.f32x2, plain exp (no running max).
__global__ __launch_bounds__(128) void main_kernel(
    const float* __restrict__ ab,
    const float* __restrict__ gdp,
    const float* __restrict__ gsp,
    float* __restrict__ outr) {
    __shared__ float s_f2[HP * FSTR];   // 30720 B (row: 16 f2 | norm ou.x ou.y pad)

    const int tid = threadIdx.x;
    const int x0 = blockIdx.x * TX, y0 = blockIdx.y * TY;
    const int n = blockIdx.z;
    const float gd = *gdp;
    const float gs = *gsp;

    // Halo load with reflect mapping + norm precompute (3 iters of 128)
    for (int i = tid; i < HP; i += 128) {
        int hy = i / HX, hx = i - hy * HX;
        int gy = refl(y0 - RAD + hy, HH);
        int gx = refl(x0 - RAD + hx, WW);
        int gp = (n << 14) + (gy << 7) + gx;
        const float4* src = (const float4*)(g_f2 + (size_t)gp * CMID);
        float4 a0 = src[0], a1 = src[1], a2 = src[2], a3 = src[3];
        float nf2 = 0.f;
        nf2 = fmaf(a0.x, a0.x, fmaf(a0.y, a0.y, fmaf(a0.z, a0.z, fmaf(a0.w, a0.w, nf2))));
        nf2 = fmaf(a1.x, a1.x, fmaf(a1.y, a1.y, fmaf(a1.z, a1.z, fmaf(a1.w, a1.w, nf2))));
        nf2 = fmaf(a2.x, a2.x, fmaf(a2.y, a2.y, fmaf(a2.z, a2.z, fmaf(a2.w, a2.w, nf2))));
        nf2 = fmaf(a3.x, a3.x, fmaf(a3.y, a3.y, fmaf(a3.z, a3.z, fmaf(a3.w, a3.w, nf2))));
        float4* dst = (float4*)(s_f2 + i * FSTR);   // 80B stride, 16B aligned
        dst[0] = a0; dst[1] = a1; dst[2] = a2; dst[3] = a3;
        float2 ov = *(const float2*)(g_oup + (size_t)gp * 2);
        dst[4] = make_float4(-gd * nf2, ov.x, ov.y, 0.f);
    }
    __syncthreads();

    const int px = tid & 15, py = tid >> 4;
    const int yx = ((y0 + py) << 7) + (x0 + px);
    const int p = (n << 14) + yx;

    // f1 scaled by 2*gd, packed in pairs; |f1|^2 for the -gd*|f1|^2 term
    u64 f1s[8];
    float nf1 = 0.f;
    {
        const float4* f1p = (const float4*)(g_f1 + (size_t)p * CMID);
        const float tg = 2.f * gd;
#pragma unroll
        for (int j = 0; j < 4; j++) {
            float4 v = f1p[j];
            nf1 = fmaf(v.x, v.x, fmaf(v.y, v.y, fmaf(v.z, v.z, fmaf(v.w, v.w, nf1))));
            f1s[2 * j + 0] = pack2(tg * v.x, tg * v.y);
            f1s[2 * j + 1] = pack2(tg * v.z, tg * v.w);
        }
    }
    const float c1 = -gd * nf1;

    const float* abp = ab + (size_t)n * 81 * HWSZ + yx;
    float s = 0.f, a0 = 0.f, a1 = 0.f;

#pragma unroll 1
    for (int dy = 0; dy < 9; dy++) {
        const float* rowab = abp + (size_t)(dy * 9) * HWSZ;
        const float* rowsh = s_f2 + ((py + dy) * HX + px) * FSTR;
        // prefetch all 9 ab values of this row (batched LDG, MLP=9)
        float abv[9];
#pragma unroll
        for (int dx = 0; dx < 9; dx++) abv[dx] = __ldg(rowab + (size_t)dx * HWSZ);
#pragma unroll
        for (int dx = 0; dx < 9; dx++) {
            const ulonglong2* fp = (const ulonglong2*)(rowsh + dx * FSTR);
            ulonglong2 q0 = fp[0], q1 = fp[1];
            u64 A = fma2(f1s[0], q0.x, 0ULL);
            u64 B = fma2(f1s[1], q0.y, 0ULL);
            A = fma2(f1s[2], q1.x, A);
            B = fma2(f1s[3], q1.y, B);
            ulonglong2 q2 = fp[2], q3 = fp[3];
            A = fma2(f1s[4], q2.x, A);
            B = fma2(f1s[5], q2.y, B);
            A = fma2(f1s[6], q3.x, A);
            B = fma2(f1s[7], q3.y, B);
            float4 oc = *(const float4*)(rowsh + dx * FSTR + 16);  // norm, ou.x, ou.y
            A = add2(A, B);
            float2 dp = unpack2(A);
            float logit = fmaf(gs, abv[dx], c1 + oc.x + dp.x + dp.y);
            float w = __expf(logit);
            s += w;
            a0 = fmaf(w, oc.y, a0);
            a1 = fmaf(w, oc.z, a1);
        }
    }

    float inv = 1.f / s;
    outr[((size_t)(n * 2) << 14) + yx] = a0 * inv;
    outr[((size_t)(n * 2 + 1) << 14) + yx] = a1 * inv;
}

extern "C" void kernel_launch(void* const* d_in, const int* in_sizes, int n_in,
                              void* d_out, int out_size) {
    const float* delta = (const float*)d_in[0];
    const float* outc  = (const float*)d_in[1];
    const float* ab    = (const float*)d_in[2];
    const float* w1    = (const float*)d_in[3];
    const float* b1    = (const float*)d_in[4];
    const float* w2    = (const float*)d_in[5];
    const float* b2    = (const float*)d_in[6];
    const float* gd    = (const float*)d_in[7];
    const float* gs    = (const float*)d_in[8];

    int N = in_sizes[0] / (CIN * HWSZ);
    if (N > NMAX) N = NMAX;

    prep_kernel<<<(N * HWSZ + 127) / 128, 128>>>(delta, outc, w1, b1, w2, b2, N);
    main_kernel<<<dim3(WW / TX, HH / TY, N), dim3(128)>>>(ab, gd, gs, (float*)d_out);
}